// round 5
// baseline (speedup 1.0000x reference)
#include <cuda_runtime.h>

namespace {
constexpr int kGroups   = 131072;                 // 64 * 2048
constexpr int kThreadsT = 2 * kGroups;            // 2 threads per group
constexpr int kThreads  = 256;
constexpr int kBlocks   = kThreadsT / kThreads;   // 1024
constexpr float kDT = 0.005f;
}

// [0..kBlocks-1] = per-block sum16, [kBlocks..2*kBlocks-1] = sum32
__device__ double g_partials[2 * kBlocks];
__device__ unsigned int g_sync = 0;

// ===================== packed f32x2 helpers (Blackwell FFMA2) =====================
using u64t = unsigned long long;

__device__ __forceinline__ u64t pk2(float a, float b) {
    u64t r;
    unsigned lo = __float_as_uint(a), hi = __float_as_uint(b);
    asm("mov.b64 %0, {%1, %2};" : "=l"(r) : "r"(lo), "r"(hi));
    return r;
}
__device__ __forceinline__ void upk2(u64t v, float& a, float& b) {
    unsigned lo, hi;
    asm("mov.b64 {%0, %1}, %2;" : "=r"(lo), "=r"(hi) : "l"(v));
    a = __uint_as_float(lo); b = __uint_as_float(hi);
}
__device__ __forceinline__ u64t fma2(u64t a, u64t b, u64t c) {
    u64t d;
    asm("fma.rn.f32x2 %0, %1, %2, %3;" : "=l"(d) : "l"(a), "l"(b), "l"(c));
    return d;
}
__device__ __forceinline__ u64t mul2(u64t a, u64t b) {
    u64t d;
    asm("mul.rn.f32x2 %0, %1, %2;" : "=l"(d) : "l"(a), "l"(b));
    return d;
}
__device__ __forceinline__ u64t neg2(u64t a) {
    return a ^ 0x8000000080000000ull;
}
__device__ __forceinline__ u64t cc2(float c) { return pk2(c, c); }

struct QP { u64t w, x, y, z; };   // two quaternions packed lane-wise

// packed Hamilton product: r = a (x) b in both SIMD lanes
__device__ __forceinline__ QP qmul2(const QP& a, const QP& b) {
    u64t nbx = neg2(b.x), nby = neg2(b.y), nbz = neg2(b.z);
    QP r;
    r.w = fma2(a.w, b.w, fma2(a.x, nbx, fma2(a.y, nby, mul2(a.z, nbz))));
    r.x = fma2(a.w, b.x, fma2(a.x, b.w, fma2(a.y, b.z, mul2(a.z, nby))));
    r.y = fma2(a.w, b.y, fma2(a.x, nbz, fma2(a.y, b.w, mul2(a.z, b.x))));
    r.z = fma2(a.w, b.z, fma2(a.x, b.y, fma2(a.y, nbx, mul2(a.z, b.w))));
    return r;
}

// packed exp of SMALL rotation vector phi = kDT * u (|phi| <= ~0.05), kDT folded in.
__device__ __forceinline__ QP exp2q(u64t ux, u64t uy, u64t uz) {
    u64t n2 = fma2(ux, ux, fma2(uy, uy, mul2(uz, uz)));
    u64t h2 = mul2(n2, cc2(0.25f * kDT * kDT));            // (|phi|/2)^2
    QP q;
    q.w = fma2(h2, fma2(h2, cc2(1.0f / 24.0f), cc2(-0.5f)), cc2(1.0f));
    u64t s = fma2(h2, fma2(h2, cc2(kDT / 240.0f), cc2(-kDT / 12.0f)), cc2(0.5f * kDT));
    q.x = mul2(s, ux); q.y = mul2(s, uy); q.z = mul2(s, uz);
    return q;
}

// ===================== scalar helpers =====================
__device__ __forceinline__ void qmul(float aw, float ax, float ay, float az,
                                     float bw, float bx, float by, float bz,
                                     float& w, float& x, float& y, float& z) {
    w = aw*bw - ax*bx - ay*by - az*bz;
    x = aw*bx + ax*bw + ay*bz - az*by;
    y = aw*by - ax*bz + ay*bw + az*bx;
    z = aw*bz + ax*by - ay*bx + az*bw;
}

// atan2(n, w) for n >= 0, w >= 0 (result in [0, pi/2]); ~1e-7 rad
__device__ __forceinline__ float atan2_pos(float n, float w) {
    bool swap = n > w;
    float num = swap ? w : n;
    float den = swap ? n : w;
    float q  = __fdividef(num, den);              // [0, 1]
    float q2 = q * q;
    float p =                     -0.0040540580734172f;
    p = fmaf(p, q2,  0.0218612288251226f);
    p = fmaf(p, q2, -0.0559098861838105f);
    p = fmaf(p, q2,  0.0964200441046623f);
    p = fmaf(p, q2, -0.1390853351676372f);
    p = fmaf(p, q2,  0.1994653599057577f);
    p = fmaf(p, q2, -0.3332985605689738f);
    p = fmaf(p, q2,  0.9999993329093277f);
    float a = p * q;
    return swap ? (1.5707963267948966f - a) : a;
}

// rs = log( R(a)^T R(b) );  returns sum_k SmoothL1(rs_k / HUBER)
__device__ __forceinline__ float log_huber_q(float aw, float ax, float ay, float az,
                                             float bw, float bx, float by, float bz) {
    float w = aw*bw + ax*bx + ay*by + az*bz;      // conj(a) (x) b
    float x = aw*bx - ax*bw - ay*bz + az*by;
    float y = aw*by + ax*bz - ay*bw - az*bx;
    float z = aw*bz - ax*by + ay*bx - az*bw;
    if (w < 0.0f) { w = -w; x = -x; y = -y; z = -z; }
    float n2 = fmaf(x, x, fmaf(y, y, z * z));
    float n  = sqrtf(n2);
    float ang = 2.0f * atan2_pos(n, w);           // [0, pi]
    float coef = __fdividef(ang, fmaxf(n, 1e-20f));
    float r0 = coef * x, r1 = coef * y, r2 = coef * z;

    float sum = 0.0f;
#pragma unroll
    for (int k = 0; k < 3; k++) {
        float r = (k == 0) ? r0 : ((k == 1) ? r1 : r2);
        float xx = r * 200.0f;                    // / HUBER
        float axv = fabsf(xx);
        sum += (axv < 1.0f) ? (0.5f * xx * xx) : (axv - 0.5f);
    }
    return sum;
}

__global__ void __launch_bounds__(kThreads)
dg_loss_kernel(const float* __restrict__ w_hat, const float* __restrict__ dw16,
               float* __restrict__ out) {
    const int t    = blockIdx.x * kThreads + threadIdx.x;  // 0 .. 262143
    const int m    = t >> 1;                               // group id
    const int g    = m & 2047;                             // group index in row
    const int half = t & 1;                                // which 8-sample half
    const bool mEven = (m & 1) == 0;

    // ---- issue all loads first (MLP) ----
    const float4* base = reinterpret_cast<const float4*>(w_hat) + (size_t)t * 6;
    float4 a0 = base[0], a1 = base[1], a2 = base[2];
    float4 b0 = base[3], b1 = base[4], b2 = base[5];
    float4 d  = reinterpret_cast<const float4*>(dw16)[(size_t)m * 12];

    // ---- compose 8 increments as TWO packed 4-chains (f32x2 SIMD) ----
    // lane .lo = increments 0..3 (floats a*), lane .hi = increments 4..7 (floats b*)
    float qw, qx, qy, qz;
    {
        QP e0 = exp2q(pk2(a0.x, b0.x), pk2(a0.y, b0.y), pk2(a0.z, b0.z));
        QP e1 = exp2q(pk2(a0.w, b0.w), pk2(a1.x, b1.x), pk2(a1.y, b1.y));
        QP e2 = exp2q(pk2(a1.z, b1.z), pk2(a1.w, b1.w), pk2(a2.x, b2.x));
        QP e3 = exp2q(pk2(a2.y, b2.y), pk2(a2.z, b2.z), pk2(a2.w, b2.w));
        QP q01 = qmul2(e0, e1);
        QP q23 = qmul2(e2, e3);
        QP qA  = qmul2(q01, q23);                // (.lo, .hi) = (prod 0..3, prod 4..7)
        float lw, hw, lx, hx, ly, hy, lz, hz;
        upk2(qA.w, lw, hw); upk2(qA.x, lx, hx);
        upk2(qA.y, ly, hy); upk2(qA.z, lz, hz);
        qmul(lw, lx, ly, lz, hw, hx, hy, hz, qw, qx, qy, qz);   // this thread's 8-product
    }

    // ---- combine halves: full = lo (x) hi (bitwise identical on both lanes) ----
    {
        float pw = __shfl_xor_sync(0xFFFFFFFFu, qw, 1);
        float px = __shfl_xor_sync(0xFFFFFFFFu, qx, 1);
        float py = __shfl_xor_sync(0xFFFFFFFFu, qy, 1);
        float pz = __shfl_xor_sync(0xFFFFFFFFu, qz, 1);
        float aw = half ? pw : qw, ax = half ? px : qx,
              ay = half ? py : qy, az = half ? pz : qz;
        float bw = half ? qw : pw, bx = half ? qx : px,
              by = half ? qy : py, bz = half ? qz : pz;
        qmul(aw, ax, ay, az, bw, bx, by, bz, qw, qx, qy, qz);
    }

    // ---- ground-truth increment for group m (all lanes, uniform) ----
    float pw, px, py, pz;
    {
        float n2 = fmaf(d.x, d.x, fmaf(d.y, d.y, d.z * d.z));
        float th = sqrtf(n2);
        float s, c;
        __sincosf(0.5f * th, &s, &c);
        float k = (th > 1e-7f) ? __fdividef(s, th) : 0.5f;
        pw = c; px = k * d.x; py = k * d.y; pz = k * d.z;
    }

    // ---- exchange with partner group (m ^ 1): lanes t <-> t^2 ----
    float qwP = __shfl_xor_sync(0xFFFFFFFFu, qw, 2);
    float qxP = __shfl_xor_sync(0xFFFFFFFFu, qx, 2);
    float qyP = __shfl_xor_sync(0xFFFFFFFFu, qy, 2);
    float qzP = __shfl_xor_sync(0xFFFFFFFFu, qz, 2);
    float pwP = __shfl_xor_sync(0xFFFFFFFFu, pw, 2);
    float pxP = __shfl_xor_sync(0xFFFFFFFFu, px, 2);
    float pyP = __shfl_xor_sync(0xFFFFFFFFu, py, 2);
    float pzP = __shfl_xor_sync(0xFFFFFFFFu, pz, 2);

    // ---- ONE log/huber pass, lane-specialized ----
    float Aw, Ax, Ay, Az, Bw, Bx, By, Bz;
    if (half == 0) {
        Aw = qw; Ax = qx; Ay = qy; Az = qz;
        Bw = pw; Bx = px; By = py; Bz = pz;
    } else {
        qmul(qw, qx, qy, qz, qwP, qxP, qyP, qzP, Aw, Ax, Ay, Az);  // hat pair
        qmul(pw, px, py, pz, pwP, pxP, pyP, pzP, Bw, Bx, By, Bz);  // gt pair
    }
    float val = log_huber_q(Aw, Ax, Ay, Az, Bw, Bx, By, Bz);

    float s16 = (half == 0 && g >= 5) ? val : 0.0f;
    float s32 = (half == 1 && mEven && g >= 10) ? val : 0.0f;

    // ---- deterministic block reduction ----
#pragma unroll
    for (int off = 16; off > 0; off >>= 1) {
        s16 += __shfl_down_sync(0xFFFFFFFFu, s16, off);
        s32 += __shfl_down_sync(0xFFFFFFFFu, s32, off);
    }
    __shared__ float w16[kThreads / 32], w32[kThreads / 32];
    __shared__ double sa[kThreads], sb[kThreads];
    __shared__ bool isLast;
    int lane = threadIdx.x & 31, wid = threadIdx.x >> 5;
    if (lane == 0) { w16[wid] = s16; w32[wid] = s32; }
    __syncthreads();
    if (threadIdx.x == 0) {
        float a = 0.0f, b = 0.0f;
#pragma unroll
        for (int i = 0; i < kThreads / 32; i++) { a += w16[i]; b += w32[i]; }
        g_partials[blockIdx.x] = (double)a;
        g_partials[kBlocks + blockIdx.x] = (double)b;
        __threadfence();
        unsigned prev = atomicAdd(&g_sync, 1u);
        isLast = (prev == (unsigned)(kBlocks - 1));
    }
    __syncthreads();

    // ---- last block: fixed-order final sum => deterministic ----
    if (isLast) {
        __threadfence();
        int tt = threadIdx.x;
        double a = 0.0, b = 0.0;
#pragma unroll
        for (int j = 0; j < kBlocks / kThreads; j++) {
            a += g_partials[tt + j * kThreads];
            b += g_partials[kBlocks + tt + j * kThreads];
        }
        sa[tt] = a; sb[tt] = b;
        __syncthreads();
        for (int off = 128; off > 0; off >>= 1) {
            if (tt < off) { sa[tt] += sa[tt + off]; sb[tt] += sb[tt + off]; }
            __syncthreads();
        }
        if (tt == 0) {
            // W * HUBER^2 = 25;  loss16 denom 64*2043*3;  loss32 denom 64*1019*3*4
            double l16 = 25.0 * sa[0] / 392256.0;
            double l32 = 25.0 * sb[0] / 782592.0;
            out[0] = (float)(l16 + l32);
            g_sync = 0;                          // reset for next graph replay
        }
    }
}

extern "C" void kernel_launch(void* const* d_in, const int* in_sizes, int n_in,
                              void* d_out, int out_size) {
    const float* w_hat = (const float*)d_in[0];
    const float* dw16  = (const float*)d_in[1];
    float* out = (float*)d_out;
    dg_loss_kernel<<<kBlocks, kThreads>>>(w_hat, dw16, out);
}

// round 6
// speedup vs baseline: 1.1282x; 1.1282x over previous
#include <cuda_runtime.h>

namespace {
constexpr int kGroups   = 131072;                 // 64 * 2048
constexpr int kThreadsT = 2 * kGroups;            // 2 threads per group
constexpr int kThreads  = 256;
constexpr int kBlocks   = kThreadsT / kThreads;   // 1024
constexpr float kDT = 0.005f;
}

// [0..kBlocks-1] = per-block sum16, [kBlocks..2*kBlocks-1] = sum32
__device__ double g_partials[2 * kBlocks];
__device__ unsigned int g_sync = 0;

__device__ __forceinline__ void qmul(float aw, float ax, float ay, float az,
                                     float bw, float bx, float by, float bz,
                                     float& w, float& x, float& y, float& z) {
    w = aw*bw - ax*bx - ay*by - az*bz;
    x = aw*bx + ax*bw + ay*bz - az*by;
    y = aw*by - ax*bz + ay*bw + az*bx;
    z = aw*bz + ax*by - ay*bx + az*bw;
}

// exp of phi = kDT * u as unit quaternion, |phi| <= ~0.15: even-poly, branch-free.
__device__ __forceinline__ void exp_quat_dt(float ux, float uy, float uz,
                                            float& w, float& x, float& y, float& z) {
    float n2 = fmaf(ux, ux, fmaf(uy, uy, uz * uz));
    float h2 = (0.25f * kDT * kDT) * n2;                    // (|phi|/2)^2
    w = fmaf(h2, fmaf(h2, (1.0f / 24.0f), -0.5f), 1.0f);
    float s = fmaf(h2, fmaf(h2, (kDT / 240.0f), -(kDT / 12.0f)), 0.5f * kDT);
    x = s * ux; y = s * uy; z = s * uz;                     // s = sin(h)/|u|
}

// atan2(n, w) for n >= 0, w >= 0 (result in [0, pi/2]); ~1e-7 rad
__device__ __forceinline__ float atan2_pos(float n, float w) {
    bool swap = n > w;
    float num = swap ? w : n;
    float den = swap ? n : w;
    float q  = __fdividef(num, den);              // [0, 1]
    float q2 = q * q;
    float p =                     -0.0040540580734172f;
    p = fmaf(p, q2,  0.0218612288251226f);
    p = fmaf(p, q2, -0.0559098861838105f);
    p = fmaf(p, q2,  0.0964200441046623f);
    p = fmaf(p, q2, -0.1390853351676372f);
    p = fmaf(p, q2,  0.1994653599057577f);
    p = fmaf(p, q2, -0.3332985605689738f);
    p = fmaf(p, q2,  0.9999993329093277f);
    float a = p * q;
    return swap ? (1.5707963267948966f - a) : a;
}

// rs = log( R(a)^T R(b) );  returns sum_k SmoothL1(rs_k / HUBER)
__device__ __forceinline__ float log_huber_q(float aw, float ax, float ay, float az,
                                             float bw, float bx, float by, float bz) {
    float w = aw*bw + ax*bx + ay*by + az*bz;      // conj(a) (x) b
    float x = aw*bx - ax*bw - ay*bz + az*by;
    float y = aw*by + ax*bz - ay*bw - az*bx;
    float z = aw*bz - ax*by + ay*bx - az*bw;
    if (w < 0.0f) { w = -w; x = -x; y = -y; z = -z; }
    float n2 = fmaf(x, x, fmaf(y, y, z * z));
    float n  = sqrtf(n2);
    float ang = 2.0f * atan2_pos(n, w);           // [0, pi]
    float coef = __fdividef(ang, fmaxf(n, 1e-20f));
    float r0 = coef * x, r1 = coef * y, r2 = coef * z;

    float sum = 0.0f;
#pragma unroll
    for (int k = 0; k < 3; k++) {
        float r = (k == 0) ? r0 : ((k == 1) ? r1 : r2);
        float xx = r * 200.0f;                    // / HUBER
        float axv = fabsf(xx);
        sum += (axv < 1.0f) ? (0.5f * xx * xx) : (axv - 0.5f);
    }
    return sum;
}

__global__ void __launch_bounds__(kThreads)
dg_loss_kernel(const float* __restrict__ w_hat, const float* __restrict__ dw16,
               float* __restrict__ out) {
    const int t    = blockIdx.x * kThreads + threadIdx.x;  // 0 .. 262143
    const int m    = t >> 1;                               // group id
    const int g    = m & 2047;                             // group index in row
    const int half = t & 1;                                // which 8-sample half
    const bool mEven = (m & 1) == 0;

    // ---- issue all loads first (MLP) ----
    const float4* base = reinterpret_cast<const float4*>(w_hat) + (size_t)t * 6;
    float4 a0 = base[0], a1 = base[1], a2 = base[2];
    float4 b0 = base[3], b1 = base[4], b2 = base[5];
    float4 d  = reinterpret_cast<const float4*>(dw16)[(size_t)m * 12];

    // ---- first-order (BCH) composition: sum this half's 8 rotation vectors ----
    float ux = ((a0.x + a0.w) + (a1.z + a2.y)) + ((b0.x + b0.w) + (b1.z + b2.y));
    float uy = ((a0.y + a1.x) + (a1.w + a2.z)) + ((b0.y + b1.x) + (b1.w + b2.z));
    float uz = ((a0.z + a1.y) + (a2.x + a2.w)) + ((b0.z + b1.y) + (b2.x + b2.w));

    // ---- combine halves: both lanes compute identical full-group sum ----
    ux += __shfl_xor_sync(0xFFFFFFFFu, ux, 1);
    uy += __shfl_xor_sync(0xFFFFFFFFu, uy, 1);
    uz += __shfl_xor_sync(0xFFFFFFFFu, uz, 1);

    float qw, qx, qy, qz;
    exp_quat_dt(ux, uy, uz, qw, qx, qy, qz);      // qhat for group m

    // ---- ground-truth increment for group m (all lanes, uniform) ----
    float pw, px, py, pz;
    {
        float n2 = fmaf(d.x, d.x, fmaf(d.y, d.y, d.z * d.z));
        float th = sqrtf(n2);
        float s, c;
        __sincosf(0.5f * th, &s, &c);
        float k = (th > 1e-7f) ? __fdividef(s, th) : 0.5f;
        pw = c; px = k * d.x; py = k * d.y; pz = k * d.z;
    }

    // ---- exchange with partner group (m ^ 1): lanes t <-> t^2 ----
    float qwP = __shfl_xor_sync(0xFFFFFFFFu, qw, 2);
    float qxP = __shfl_xor_sync(0xFFFFFFFFu, qx, 2);
    float qyP = __shfl_xor_sync(0xFFFFFFFFu, qy, 2);
    float qzP = __shfl_xor_sync(0xFFFFFFFFu, qz, 2);
    float pwP = __shfl_xor_sync(0xFFFFFFFFu, pw, 2);
    float pxP = __shfl_xor_sync(0xFFFFFFFFu, px, 2);
    float pyP = __shfl_xor_sync(0xFFFFFFFFu, py, 2);
    float pzP = __shfl_xor_sync(0xFFFFFFFFu, pz, 2);

    // ---- ONE log/huber pass, lane-specialized ----
    // even lanes: 16-level (qhat_m vs gt_m)
    // lanes == 1 mod 4: 32-level pair (q_m(x)q_{m+1} vs gt_m(x)gt_{m+1}), exact qmul
    float Aw, Ax, Ay, Az, Bw, Bx, By, Bz;
    if (half == 0) {
        Aw = qw; Ax = qx; Ay = qy; Az = qz;
        Bw = pw; Bx = px; By = py; Bz = pz;
    } else {
        qmul(qw, qx, qy, qz, qwP, qxP, qyP, qzP, Aw, Ax, Ay, Az);  // hat pair
        qmul(pw, px, py, pz, pwP, pxP, pyP, pzP, Bw, Bx, By, Bz);  // gt pair
    }
    float val = log_huber_q(Aw, Ax, Ay, Az, Bw, Bx, By, Bz);

    float s16 = (half == 0 && g >= 5) ? val : 0.0f;
    float s32 = (half == 1 && mEven && g >= 10) ? val : 0.0f;

    // ---- deterministic block reduction ----
#pragma unroll
    for (int off = 16; off > 0; off >>= 1) {
        s16 += __shfl_down_sync(0xFFFFFFFFu, s16, off);
        s32 += __shfl_down_sync(0xFFFFFFFFu, s32, off);
    }
    __shared__ float w16[kThreads / 32], w32[kThreads / 32];
    __shared__ double sa[kThreads], sb[kThreads];
    __shared__ bool isLast;
    int lane = threadIdx.x & 31, wid = threadIdx.x >> 5;
    if (lane == 0) { w16[wid] = s16; w32[wid] = s32; }
    __syncthreads();
    if (threadIdx.x == 0) {
        float a = 0.0f, b = 0.0f;
#pragma unroll
        for (int i = 0; i < kThreads / 32; i++) { a += w16[i]; b += w32[i]; }
        g_partials[blockIdx.x] = (double)a;
        g_partials[kBlocks + blockIdx.x] = (double)b;
        __threadfence();
        unsigned prev = atomicAdd(&g_sync, 1u);
        isLast = (prev == (unsigned)(kBlocks - 1));
    }
    __syncthreads();

    // ---- last block: fixed-order final sum => deterministic ----
    if (isLast) {
        __threadfence();
        int tt = threadIdx.x;
        double a = 0.0, b = 0.0;
#pragma unroll
        for (int j = 0; j < kBlocks / kThreads; j++) {
            a += g_partials[tt + j * kThreads];
            b += g_partials[kBlocks + tt + j * kThreads];
        }
        sa[tt] = a; sb[tt] = b;
        __syncthreads();
        for (int off = 128; off > 0; off >>= 1) {
            if (tt < off) { sa[tt] += sa[tt + off]; sb[tt] += sb[tt + off]; }
            __syncthreads();
        }
        if (tt == 0) {
            // W * HUBER^2 = 25;  loss16 denom 64*2043*3;  loss32 denom 64*1019*3*4
            double l16 = 25.0 * sa[0] / 392256.0;
            double l32 = 25.0 * sb[0] / 782592.0;
            out[0] = (float)(l16 + l32);
            g_sync = 0;                          // reset for next graph replay
        }
    }
}

extern "C" void kernel_launch(void* const* d_in, const int* in_sizes, int n_in,
                              void* d_out, int out_size) {
    const float* w_hat = (const float*)d_in[0];
    const float* dw16  = (const float*)d_in[1];
    float* out = (float*)d_out;
    dg_loss_kernel<<<kBlocks, kThreads>>>(w_hat, dw16, out);
}